// round 7
// baseline (speedup 1.0000x reference)
#include <cuda_runtime.h>
#include <cuda_fp16.h>
#include <cstdint>
#include <math.h>

// ---------------- scratch (no allocations allowed) ----------------
#define N_LEAVES_MAX 100000
#define MAXB 256
#define GRID_B 148

__device__ __align__(16) __half g_dleaf[N_LEAVES_MAX + 128];
__device__ int    g_maxint;          // max d as ordered int (positive floats)
__device__ float4 g_part[MAXB];      // (sum_exp, sum_sims_exp, sum_sims, -)

// ---------------- mbarrier / bulk-copy helpers (kernel B staging) ----------------
__device__ __forceinline__ void mbar_init(unsigned int mbar, unsigned int cnt) {
    asm volatile("mbarrier.init.shared.b64 [%0], %1;" :: "r"(mbar), "r"(cnt) : "memory");
}
__device__ __forceinline__ void mbar_expect_tx(unsigned int mbar, unsigned int bytes) {
    asm volatile("mbarrier.arrive.expect_tx.shared.b64 _, [%0], %1;"
                 :: "r"(mbar), "r"(bytes) : "memory");
}
__device__ __forceinline__ void mbar_wait(unsigned int mbar, unsigned int phase) {
    asm volatile(
        "{\n\t"
        ".reg .pred P1;\n\t"
        "WAIT_LOOP_%=:\n\t"
        "mbarrier.try_wait.parity.acquire.cta.shared::cta.b64 P1, [%0], %1, 0x989680;\n\t"
        "@P1 bra.uni WAIT_DONE_%=;\n\t"
        "bra.uni WAIT_LOOP_%=;\n\t"
        "WAIT_DONE_%=:\n\t"
        "}"
        :: "r"(mbar), "r"(phase) : "memory");
}
__device__ __forceinline__ void bulk_g2s(unsigned int dst, const void* src,
                                         unsigned int bytes, unsigned int mbar) {
    asm volatile(
        "cp.async.bulk.shared::cluster.global.mbarrier::complete_tx::bytes [%0], [%1], %2, [%3];"
        :: "r"(dst), "l"(src), "r"(bytes), "r"(mbar) : "memory");
}

#define TILE_A 128   // leaves per block

// ---------------- Kernel A: LDG->reg->STS, 3 blocks/SM ----------------
// One tile of 128 leaves per block. Coalesced LDG.128 into registers, STS with
// rotation swizzle (slot = r*32 + (c+r)&31): conflict-free stores, conflict-free
// per-lane row reads, broadcast e-vector reads.
__global__ __launch_bounds__(128, 3) void leaf_dist_kernel(
        const int* __restrict__ lca,
        const float* __restrict__ emb,
        const float* __restrict__ leaves,
        const float* __restrict__ scale,
        int n_leaves)
{
    extern __shared__ __align__(16) float4 s_y[];   // [TILE_A*32] swizzled
    __shared__ __align__(16) float s_e[128];
    __shared__ float s_red[128];
    __shared__ float s_nx, s_inv;

    const int t     = threadIdx.x;
    const int leaf0 = blockIdx.x * TILE_A;
    const int valid = min(TILE_A, n_leaves - leaf0);
    const int nf4   = valid * 32;                   // float4s in this tile

    // ---- stage tile: coalesced LDG.128 -> swizzled STS ----
    const float4* src = reinterpret_cast<const float4*>(leaves) + (size_t)leaf0 * 32;
    #pragma unroll
    for (int j = 0; j < 32; j++) {
        int idx = t + j * 128;
        if (idx < nf4) {
            float4 v = src[idx];
            int r = idx >> 5, c = idx & 31;
            s_y[r * 32 + ((c + r) & 31)] = v;
        }
    }

    // ---- build e1 = emb[lca]/max(||.||,1e-12) * clip(scale) ----
    const float* erow = emb + (long long)lca[0] * 128;
    float w = erow[t];
    s_red[t] = w * w;
    __syncthreads();
    for (int off = 64; off > 0; off >>= 1) {
        if (t < off) s_red[t] += s_red[t + off];
        __syncthreads();
    }
    if (t == 0) {
        float norm2  = s_red[0];
        float s      = fminf(fmaxf(scale[0], 0.01f), 1.0f - 0.001f);
        float factor = s / fmaxf(sqrtf(norm2), 1e-12f);
        float nx     = factor * factor * norm2;
        s_nx  = nx;
        s_inv = 1.0f / (1.0f - nx);
        s_red[0] = factor;
    }
    __syncthreads();
    s_e[t] = w * s_red[0];
    __syncthreads();      // tile + e + constants visible

    // ---- thread-per-leaf compute ----
    float dmax = 0.0f;
    const float4* er = reinterpret_cast<const float4*>(s_e);
    if (t < valid) {
        const float4* yr = s_y + t * 32;
        float dot = 0.0f, ny = 0.0f;
        #pragma unroll
        for (int k = 0; k < 32; k++) {
            float4 y = yr[(k + t) & 31];   // logical col k of row t (swizzled)
            float4 e = er[k];              // broadcast
            dot = fmaf(e.x, y.x, fmaf(e.y, y.y, fmaf(e.z, y.z, fmaf(e.w, y.w, dot))));
            ny  = fmaf(y.x, y.x, fmaf(y.y, y.y, fmaf(y.z, y.z, fmaf(y.w, y.w, ny))));
        }
        float sq  = s_nx - 2.0f * dot + ny;
        float arg = 1.0f + 2.0f * sq * s_inv / (1.0f - ny);
        arg = fmaxf(arg, 1.0f + 1e-7f);
        float d = acoshf(arg);
        g_dleaf[leaf0 + t] = __float2half(d);
        dmax = d;
    }

    // ---- block max -> global atomicMax (deterministic) ----
    s_red[t] = dmax;
    __syncthreads();
    for (int off = 64; off > 0; off >>= 1) {
        if (t < off) s_red[t] = fmaxf(s_red[t], s_red[t + off]);
        __syncthreads();
    }
    if (t == 0) atomicMax(&g_maxint, __float_as_int(s_red[0]));
}

// ---------------- Kernel B: branchless softmax partial sums ----------------
__global__ __launch_bounds__(1024) void pair_reduce_kernel(
        const int* __restrict__ l_idx,
        const int* __restrict__ r_idx,
        const float* __restrict__ sims,
        int n_pairs, int n_leaves)
{
    extern __shared__ __half s_tab[];
    __shared__ float r_se[1024], r_ss[1024], r_su[1024];
    __shared__ __align__(8) unsigned long long s_mbar;

    const int t = threadIdx.x;
    const unsigned int sb  = (unsigned int)__cvta_generic_to_shared(s_tab);
    const unsigned int mbr = (unsigned int)__cvta_generic_to_shared(&s_mbar);

    const unsigned int totr  = ((unsigned int)n_leaves * 2u + 127u) & ~127u;
    const unsigned int chunk = totr / 8u;

    if (t == 0) { mbar_init(mbr, 1); mbar_expect_tx(mbr, totr); }
    __syncthreads();
    if (t < 8)
        bulk_g2s(sb + t * chunk, reinterpret_cast<const char*>(g_dleaf) + t * chunk,
                 chunk, mbr);

    const float M = 40.0f * __int_as_float(g_maxint);

    mbar_wait(mbr, 0);

    float se = 0.0f, ss = 0.0f, su = 0.0f;

    const int n4 = n_pairs >> 2;
    const int4*   l4 = reinterpret_cast<const int4*>(l_idx);
    const int4*   r4 = reinterpret_cast<const int4*>(r_idx);
    const float4* s4 = reinterpret_cast<const float4*>(sims);
    const int stride = gridDim.x * blockDim.x;

    #pragma unroll 2
    for (int i = blockIdx.x * blockDim.x + t; i < n4; i += stride) {
        int4   li = l4[i];
        int4   ri = r4[i];
        float4 si = s4[i];
        float e0 = __expf(fmaf(20.0f, __half2float(s_tab[li.x]) + __half2float(s_tab[ri.x]), -M));
        float e1 = __expf(fmaf(20.0f, __half2float(s_tab[li.y]) + __half2float(s_tab[ri.y]), -M));
        float e2 = __expf(fmaf(20.0f, __half2float(s_tab[li.z]) + __half2float(s_tab[ri.z]), -M));
        float e3 = __expf(fmaf(20.0f, __half2float(s_tab[li.w]) + __half2float(s_tab[ri.w]), -M));
        se += (e0 + e1) + (e2 + e3);
        ss  = fmaf(si.x, e0, fmaf(si.y, e1, fmaf(si.z, e2, fmaf(si.w, e3, ss))));
        su += (si.x + si.y) + (si.z + si.w);
    }
    // scalar tail
    if (blockIdx.x == 0) {
        for (int i = n4 * 4 + t; i < n_pairs; i += blockDim.x) {
            float e = __expf(fmaf(20.0f,
                        __half2float(s_tab[l_idx[i]]) + __half2float(s_tab[r_idx[i]]), -M));
            float si = sims[i];
            se += e; ss = fmaf(si, e, ss); su += si;
        }
    }

    r_se[t] = se; r_ss[t] = ss; r_su[t] = su;
    __syncthreads();
    for (int off = 512; off > 0; off >>= 1) {
        if (t < off) {
            r_se[t] += r_se[t + off];
            r_ss[t] += r_ss[t + off];
            r_su[t] += r_su[t + off];
        }
        __syncthreads();
    }
    if (t == 0) g_part[blockIdx.x] = make_float4(r_se[0], r_ss[0], r_su[0], 0.0f);
}

// ---------------- Kernel C: finalize ----------------
__global__ void finalize_kernel(float* __restrict__ out, int nb)
{
    __shared__ float r_se[256], r_ss[256], r_su[256];
    const int t = threadIdx.x;
    float se = 0.0f, ss = 0.0f, su = 0.0f;
    for (int i = t; i < nb; i += 256) {
        float4 p = g_part[i];
        se += p.x; ss += p.y; su += p.z;
    }
    r_se[t] = se; r_ss[t] = ss; r_su[t] = su;
    __syncthreads();
    for (int off = 128; off > 0; off >>= 1) {
        if (t < off) {
            r_se[t] += r_se[t + off];
            r_ss[t] += r_ss[t + off];
            r_su[t] += r_su[t + off];
        }
        __syncthreads();
    }
    if (t == 0) out[0] = r_su[0] - r_ss[0] / r_se[0];
}

// ---------------- launch ----------------
extern "C" void kernel_launch(void* const* d_in, const int* in_sizes, int n_in,
                              void* d_out, int out_size)
{
    const int*   lca    = (const int*)  d_in[0];
    const int*   l_idx  = (const int*)  d_in[1];
    const int*   r_idx  = (const int*)  d_in[2];
    const float* sims   = (const float*)d_in[3];
    const float* emb    = (const float*)d_in[4];
    const float* leaves = (const float*)d_in[5];
    const float* scale  = (const float*)d_in[6];

    const int n_pairs  = in_sizes[1];
    const int n_leaves = in_sizes[5] / 128;

    const int smemA = TILE_A * 32 * 16;                     // 65536
    const int smemB = (n_leaves * 2 + 127) & ~127;
    cudaFuncSetAttribute(leaf_dist_kernel,
                         cudaFuncAttributeMaxDynamicSharedMemorySize, smemA);
    cudaFuncSetAttribute(pair_reduce_kernel,
                         cudaFuncAttributeMaxDynamicSharedMemorySize,
                         (N_LEAVES_MAX * 2 + 127) & ~127);

    const int blocksA = (n_leaves + TILE_A - 1) / TILE_A;
    leaf_dist_kernel<<<blocksA, 128, smemA>>>(lca, emb, leaves, scale, n_leaves);
    pair_reduce_kernel<<<GRID_B, 1024, smemB>>>(l_idx, r_idx, sims, n_pairs, n_leaves);
    finalize_kernel<<<1, 256>>>((float*)d_out, GRID_B);
}

// round 8
// speedup vs baseline: 1.0965x; 1.0965x over previous
#include <cuda_runtime.h>
#include <cuda_fp16.h>
#include <cstdint>
#include <math.h>

// ---------------- scratch (no allocations allowed) ----------------
#define N_LEAVES_MAX 100000
#define MAXB 256
#define GRID_B 148

__device__ __align__(16) __half g_dleaf[N_LEAVES_MAX + 128];
__device__ int    g_maxint;          // max d as ordered int (positive floats)
__device__ float4 g_part[MAXB];      // (sum_exp, sum_sims_exp, sum_sims, -)

// ---------------- mbarrier / bulk-copy helpers ----------------
__device__ __forceinline__ void mbar_init(unsigned int mbar, unsigned int cnt) {
    asm volatile("mbarrier.init.shared.b64 [%0], %1;" :: "r"(mbar), "r"(cnt) : "memory");
}
__device__ __forceinline__ void mbar_expect_tx(unsigned int mbar, unsigned int bytes) {
    asm volatile("mbarrier.arrive.expect_tx.shared.b64 _, [%0], %1;"
                 :: "r"(mbar), "r"(bytes) : "memory");
}
__device__ __forceinline__ void mbar_arrive(unsigned int mbar) {
    asm volatile("mbarrier.arrive.shared.b64 _, [%0];" :: "r"(mbar) : "memory");
}
__device__ __forceinline__ void mbar_wait(unsigned int mbar, unsigned int phase) {
    asm volatile(
        "{\n\t"
        ".reg .pred P1;\n\t"
        "WAIT_LOOP_%=:\n\t"
        "mbarrier.try_wait.parity.acquire.cta.shared::cta.b64 P1, [%0], %1, 0x989680;\n\t"
        "@P1 bra.uni WAIT_DONE_%=;\n\t"
        "bra.uni WAIT_LOOP_%=;\n\t"
        "WAIT_DONE_%=:\n\t"
        "}"
        :: "r"(mbar), "r"(phase) : "memory");
}
__device__ __forceinline__ void bulk_g2s(unsigned int dst, const void* src,
                                         unsigned int bytes, unsigned int mbar) {
    asm volatile(
        "cp.async.bulk.shared::cluster.global.mbarrier::complete_tx::bytes [%0], [%1], %2, [%3];"
        :: "r"(dst), "l"(src), "r"(bytes), "r"(mbar) : "memory");
}

#define TILE_A 128
#define N_STG 3
#define STAGE_BYTES (TILE_A * 512)     // 65536

// ---------------- Kernel A: warp-specialized 3-stage TMA pipeline ----------------
// 160 threads: t<128 consumers (thread-per-leaf), warp 4 producer (t==128 issues).
__global__ __launch_bounds__(160, 1) void leaf_dist_kernel(
        const int* __restrict__ lca,
        const float* __restrict__ emb,
        const float* __restrict__ leaves,
        const float* __restrict__ scale,
        int n_leaves)
{
    extern __shared__ __align__(16) float4 s_y[];       // [N_STG][TILE_A*32]
    __shared__ __align__(16) float s_e[128];
    __shared__ float s_red[128];
    __shared__ float s_nx, s_inv;
    __shared__ __align__(8) unsigned long long s_full[N_STG], s_empty[N_STG];

    const int t       = threadIdx.x;
    const int bx      = blockIdx.x;
    const int grid    = gridDim.x;
    const int n_tiles = (n_leaves + TILE_A - 1) / TILE_A;
    const unsigned int sbase = (unsigned int)__cvta_generic_to_shared(s_y);
    const unsigned int mbF   = (unsigned int)__cvta_generic_to_shared(&s_full[0]);
    const unsigned int mbE   = (unsigned int)__cvta_generic_to_shared(&s_empty[0]);

    const int my_n = (bx < n_tiles) ? (n_tiles - bx + grid - 1) / grid : 0;

    if (t == 0) {
        #pragma unroll
        for (int s = 0; s < N_STG; s++) {
            mbar_init(mbF + s * 8, 1);        // completed by TMA expect_tx
            mbar_init(mbE + s * 8, 128);      // completed by 128 consumer arrivals
        }
    }
    __syncthreads();

    // ---- prologue: fill all stages immediately (no empty-wait needed) ----
    if (t == 128) {
        #pragma unroll
        for (int p = 0; p < N_STG; p++) {
            if (p < my_n) {
                int l0 = (bx + p * grid) * TILE_A;
                unsigned int bytes = (unsigned int)min(TILE_A, n_leaves - l0) * 512u;
                mbar_expect_tx(mbF + p * 8, bytes);
                bulk_g2s(sbase + p * STAGE_BYTES, leaves + (size_t)l0 * 128,
                         bytes, mbF + p * 8);
            }
        }
    }

    // ---- build e1 while prologue copies fly (all 160 threads in syncs) ----
    const float* erow = emb + (long long)lca[0] * 128;
    float w = 0.0f;
    if (t < 128) { w = erow[t]; s_red[t] = w * w; }
    __syncthreads();
    for (int off = 64; off > 0; off >>= 1) {
        if (t < off) s_red[t] += s_red[t + off];
        __syncthreads();
    }
    if (t == 0) {
        float norm2  = s_red[0];
        float s      = fminf(fmaxf(scale[0], 0.01f), 1.0f - 0.001f);
        float factor = s / fmaxf(sqrtf(norm2), 1e-12f);
        float nx     = factor * factor * norm2;
        s_nx  = nx;
        s_inv = 1.0f / (1.0f - nx);
        s_red[0] = factor;
    }
    __syncthreads();
    if (t < 128) s_e[t] = w * s_red[0];
    __syncthreads();          // s_e/s_nx/s_inv visible to all consumers

    float dmax = 0.0f;

    if (t == 128) {
        // ---- producer: refill freed stages ----
        #pragma unroll 1
        for (int i = N_STG; i < my_n; i++) {
            const int s = i % N_STG;
            const int v = i / N_STG;
            mbar_wait(mbE + s * 8, (v & 1) ^ 1);   // per-stage parity: 1,0,1,...
            int l0 = (bx + i * grid) * TILE_A;
            unsigned int bytes = (unsigned int)min(TILE_A, n_leaves - l0) * 512u;
            mbar_expect_tx(mbF + s * 8, bytes);
            bulk_g2s(sbase + s * STAGE_BYTES, leaves + (size_t)l0 * 128,
                     bytes, mbF + s * 8);
        }
    } else if (t < 128) {
        // ---- consumers: thread-per-leaf, no block barriers ----
        const float4* er = reinterpret_cast<const float4*>(s_e);
        const float nx = s_nx, inv = s_inv;
        #pragma unroll 1
        for (int i = 0; i < my_n; i++) {
            const int s = i % N_STG;
            const int v = i / N_STG;
            mbar_wait(mbF + s * 8, v & 1);         // per-stage parity: 0,1,0,...

            const int leaf0 = (bx + i * grid) * TILE_A;
            const int valid = min(TILE_A, n_leaves - leaf0);
            if (t < valid) {
                const float4* yr = s_y + s * (STAGE_BYTES / 16) + t * 32;
                float dot = 0.0f, ny = 0.0f;
                #pragma unroll
                for (int k = 0; k < 32; k++) {
                    int kk = (k + t) & 31;         // rotation: conflict-free
                    float4 y = yr[kk];
                    float4 e = er[kk];
                    dot = fmaf(e.x, y.x, fmaf(e.y, y.y, fmaf(e.z, y.z, fmaf(e.w, y.w, dot))));
                    ny  = fmaf(y.x, y.x, fmaf(y.y, y.y, fmaf(y.z, y.z, fmaf(y.w, y.w, ny))));
                }
                float sq  = nx - 2.0f * dot + ny;
                float arg = 1.0f + 2.0f * sq * inv / (1.0f - ny);
                arg = fmaxf(arg, 1.0f + 1e-7f);
                float d = acoshf(arg);
                g_dleaf[leaf0 + t] = __float2half(d);
                dmax = fmaxf(dmax, d);
            }
            mbar_arrive(mbE + s * 8);              // free the stage
        }
    }

    // ---- block max -> global atomicMax (deterministic) ----
    if (t < 128) s_red[t] = dmax;
    __syncthreads();
    for (int off = 64; off > 0; off >>= 1) {
        if (t < off) s_red[t] = fmaxf(s_red[t], s_red[t + off]);
        __syncthreads();
    }
    if (t == 0) atomicMax(&g_maxint, __float_as_int(s_red[0]));
}

// ---------------- Kernel B: branchless softmax partial sums ----------------
__global__ __launch_bounds__(1024) void pair_reduce_kernel(
        const int* __restrict__ l_idx,
        const int* __restrict__ r_idx,
        const float* __restrict__ sims,
        int n_pairs, int n_leaves)
{
    extern __shared__ __half s_tab[];
    __shared__ float r_se[1024], r_ss[1024], r_su[1024];
    __shared__ __align__(8) unsigned long long s_mbar;

    const int t = threadIdx.x;
    const unsigned int sb  = (unsigned int)__cvta_generic_to_shared(s_tab);
    const unsigned int mbr = (unsigned int)__cvta_generic_to_shared(&s_mbar);

    const unsigned int totr  = ((unsigned int)n_leaves * 2u + 127u) & ~127u;
    const unsigned int chunk = totr / 8u;

    if (t == 0) { mbar_init(mbr, 1); mbar_expect_tx(mbr, totr); }
    __syncthreads();
    if (t < 8)
        bulk_g2s(sb + t * chunk, reinterpret_cast<const char*>(g_dleaf) + t * chunk,
                 chunk, mbr);

    const float M = 40.0f * __int_as_float(g_maxint);

    mbar_wait(mbr, 0);

    float se = 0.0f, ss = 0.0f, su = 0.0f;

    const int n4 = n_pairs >> 2;
    const int4*   l4 = reinterpret_cast<const int4*>(l_idx);
    const int4*   r4 = reinterpret_cast<const int4*>(r_idx);
    const float4* s4 = reinterpret_cast<const float4*>(sims);
    const int stride = gridDim.x * blockDim.x;

    #pragma unroll 2
    for (int i = blockIdx.x * blockDim.x + t; i < n4; i += stride) {
        int4   li = l4[i];
        int4   ri = r4[i];
        float4 si = s4[i];
        float e0 = __expf(fmaf(20.0f, __half2float(s_tab[li.x]) + __half2float(s_tab[ri.x]), -M));
        float e1 = __expf(fmaf(20.0f, __half2float(s_tab[li.y]) + __half2float(s_tab[ri.y]), -M));
        float e2 = __expf(fmaf(20.0f, __half2float(s_tab[li.z]) + __half2float(s_tab[ri.z]), -M));
        float e3 = __expf(fmaf(20.0f, __half2float(s_tab[li.w]) + __half2float(s_tab[ri.w]), -M));
        se += (e0 + e1) + (e2 + e3);
        ss  = fmaf(si.x, e0, fmaf(si.y, e1, fmaf(si.z, e2, fmaf(si.w, e3, ss))));
        su += (si.x + si.y) + (si.z + si.w);
    }
    // scalar tail
    if (blockIdx.x == 0) {
        for (int i = n4 * 4 + t; i < n_pairs; i += blockDim.x) {
            float e = __expf(fmaf(20.0f,
                        __half2float(s_tab[l_idx[i]]) + __half2float(s_tab[r_idx[i]]), -M));
            float si = sims[i];
            se += e; ss = fmaf(si, e, ss); su += si;
        }
    }

    r_se[t] = se; r_ss[t] = ss; r_su[t] = su;
    __syncthreads();
    for (int off = 512; off > 0; off >>= 1) {
        if (t < off) {
            r_se[t] += r_se[t + off];
            r_ss[t] += r_ss[t + off];
            r_su[t] += r_su[t + off];
        }
        __syncthreads();
    }
    if (t == 0) g_part[blockIdx.x] = make_float4(r_se[0], r_ss[0], r_su[0], 0.0f);
}

// ---------------- Kernel C: finalize ----------------
__global__ void finalize_kernel(float* __restrict__ out, int nb)
{
    __shared__ float r_se[256], r_ss[256], r_su[256];
    const int t = threadIdx.x;
    float se = 0.0f, ss = 0.0f, su = 0.0f;
    for (int i = t; i < nb; i += 256) {
        float4 p = g_part[i];
        se += p.x; ss += p.y; su += p.z;
    }
    r_se[t] = se; r_ss[t] = ss; r_su[t] = su;
    __syncthreads();
    for (int off = 128; off > 0; off >>= 1) {
        if (t < off) {
            r_se[t] += r_se[t + off];
            r_ss[t] += r_ss[t + off];
            r_su[t] += r_su[t + off];
        }
        __syncthreads();
    }
    if (t == 0) out[0] = r_su[0] - r_ss[0] / r_se[0];
}

// ---------------- launch ----------------
extern "C" void kernel_launch(void* const* d_in, const int* in_sizes, int n_in,
                              void* d_out, int out_size)
{
    const int*   lca    = (const int*)  d_in[0];
    const int*   l_idx  = (const int*)  d_in[1];
    const int*   r_idx  = (const int*)  d_in[2];
    const float* sims   = (const float*)d_in[3];
    const float* emb    = (const float*)d_in[4];
    const float* leaves = (const float*)d_in[5];
    const float* scale  = (const float*)d_in[6];

    const int n_pairs  = in_sizes[1];
    const int n_leaves = in_sizes[5] / 128;

    const int smemA = N_STG * STAGE_BYTES;                  // 196608
    const int smemB = (n_leaves * 2 + 127) & ~127;
    cudaFuncSetAttribute(leaf_dist_kernel,
                         cudaFuncAttributeMaxDynamicSharedMemorySize, smemA);
    cudaFuncSetAttribute(pair_reduce_kernel,
                         cudaFuncAttributeMaxDynamicSharedMemorySize,
                         (N_LEAVES_MAX * 2 + 127) & ~127);

    int sm_count = 0;
    cudaDeviceGetAttribute(&sm_count, cudaDevAttrMultiProcessorCount, 0);
    if (sm_count <= 0 || sm_count > MAXB) sm_count = 148;

    leaf_dist_kernel<<<sm_count, 160, smemA>>>(lca, emb, leaves, scale, n_leaves);
    pair_reduce_kernel<<<GRID_B, 1024, smemB>>>(l_idx, r_idx, sims, n_pairs, n_leaves);
    finalize_kernel<<<1, 256>>>((float*)d_out, GRID_B);
}

// round 9
// speedup vs baseline: 1.1082x; 1.0107x over previous
#include <cuda_runtime.h>
#include <cuda_fp16.h>
#include <cstdint>
#include <math.h>

// ---------------- scratch (no allocations allowed) ----------------
#define N_LEAVES_MAX 100000
#define MAXB 256
#define GRID_B 148

__device__ __align__(16) __half g_dleaf[N_LEAVES_MAX + 128];
__device__ int    g_maxint;          // max d as ordered int (positive floats)
__device__ float4 g_part[MAXB];      // (sum_exp, sum_sims_exp, sum_sims, -)

// ---------------- mbarrier / bulk-copy helpers (kernel B staging) ----------------
__device__ __forceinline__ void mbar_init(unsigned int mbar, unsigned int cnt) {
    asm volatile("mbarrier.init.shared.b64 [%0], %1;" :: "r"(mbar), "r"(cnt) : "memory");
}
__device__ __forceinline__ void mbar_expect_tx(unsigned int mbar, unsigned int bytes) {
    asm volatile("mbarrier.arrive.expect_tx.shared.b64 _, [%0], %1;"
                 :: "r"(mbar), "r"(bytes) : "memory");
}
__device__ __forceinline__ void mbar_wait(unsigned int mbar, unsigned int phase) {
    asm volatile(
        "{\n\t"
        ".reg .pred P1;\n\t"
        "WAIT_LOOP_%=:\n\t"
        "mbarrier.try_wait.parity.acquire.cta.shared::cta.b64 P1, [%0], %1, 0x989680;\n\t"
        "@P1 bra.uni WAIT_DONE_%=;\n\t"
        "bra.uni WAIT_LOOP_%=;\n\t"
        "WAIT_DONE_%=:\n\t"
        "}"
        :: "r"(mbar), "r"(phase) : "memory");
}
__device__ __forceinline__ void bulk_g2s(unsigned int dst, const void* src,
                                         unsigned int bytes, unsigned int mbar) {
    asm volatile(
        "cp.async.bulk.shared::cluster.global.mbarrier::complete_tx::bytes [%0], [%1], %2, [%3];"
        :: "r"(dst), "l"(src), "r"(bytes), "r"(mbar) : "memory");
}

// ---------------- Kernel A: direct-LDG streaming, 8 lanes per leaf ----------------
__global__ __launch_bounds__(256) void leaf_dist_kernel(
        const int* __restrict__ lca,
        const float* __restrict__ emb,
        const float* __restrict__ leaves,
        const float* __restrict__ scale,
        int n_leaves)
{
    __shared__ __align__(16) float s_e[128];
    __shared__ float s_red[256];
    __shared__ float s_nx, s_inv;

    const int t = threadIdx.x;

    // ---- build e1 = emb[lca]/max(||.||,1e-12) * clip(scale) ----
    const float* erow = emb + (long long)lca[0] * 128;
    float w = 0.0f;
    if (t < 128) { w = erow[t]; s_red[t] = w * w; }
    __syncthreads();
    for (int off = 64; off > 0; off >>= 1) {
        if (t < off) s_red[t] += s_red[t + off];
        __syncthreads();
    }
    if (t == 0) {
        float norm2  = s_red[0];
        float s      = fminf(fmaxf(scale[0], 0.01f), 1.0f - 0.001f);
        float factor = s / fmaxf(sqrtf(norm2), 1e-12f);
        float nx     = factor * factor * norm2;
        s_nx  = nx;
        s_inv = 1.0f / (1.0f - nx);
        s_red[0] = factor;
    }
    __syncthreads();
    if (t < 128) s_e[t] = w * s_red[0];
    __syncthreads();

    // ---- per-thread constants: 4 e-chunks (sub, sub+8, sub+16, sub+24) ----
    const int lane = t & 31;
    const int sub  = lane & 7;        // chunk-slot within the 8-lane group
    const int grp  = lane >> 3;       // which of 4 leaves this group owns
    const float4* er = reinterpret_cast<const float4*>(s_e);
    const float4 ea = er[sub], eb = er[sub + 8], ec = er[sub + 16], ed = er[sub + 24];
    const float nx = s_nx, inv = s_inv;

    const float4* leaves4 = reinterpret_cast<const float4*>(leaves);
    const int gwarp   = (blockIdx.x * blockDim.x + t) >> 5;
    const int nwarps  = (gridDim.x * blockDim.x) >> 5;
    const int ngroups = (n_leaves + 3) >> 2;

    float dmax = 0.0f;

    for (int gidx = gwarp; gidx < ngroups; gidx += nwarps) {
        const int  leaf = gidx * 4 + grp;
        const bool ok   = leaf < n_leaves;
        const float4* row = leaves4 + (size_t)(ok ? leaf : 0) * 32;

        // 4 coalesced LDG.128 (4 full 128B lines per instruction)
        float4 y0 = row[sub];
        float4 y1 = row[sub + 8];
        float4 y2 = row[sub + 16];
        float4 y3 = row[sub + 24];

        float dot, ny;
        dot  = ea.x * y0.x + ea.y * y0.y + ea.z * y0.z + ea.w * y0.w;
        ny   = y0.x * y0.x + y0.y * y0.y + y0.z * y0.z + y0.w * y0.w;
        dot  = fmaf(eb.x, y1.x, fmaf(eb.y, y1.y, fmaf(eb.z, y1.z, fmaf(eb.w, y1.w, dot))));
        ny   = fmaf(y1.x, y1.x, fmaf(y1.y, y1.y, fmaf(y1.z, y1.z, fmaf(y1.w, y1.w, ny))));
        dot  = fmaf(ec.x, y2.x, fmaf(ec.y, y2.y, fmaf(ec.z, y2.z, fmaf(ec.w, y2.w, dot))));
        ny   = fmaf(y2.x, y2.x, fmaf(y2.y, y2.y, fmaf(y2.z, y2.z, fmaf(y2.w, y2.w, ny))));
        dot  = fmaf(ed.x, y3.x, fmaf(ed.y, y3.y, fmaf(ed.z, y3.z, fmaf(ed.w, y3.w, dot))));
        ny   = fmaf(y3.x, y3.x, fmaf(y3.y, y3.y, fmaf(y3.z, y3.z, fmaf(y3.w, y3.w, ny))));

        // butterfly reduce within the 8-lane group
        #pragma unroll
        for (int o = 1; o < 8; o <<= 1) {
            dot += __shfl_xor_sync(0xffffffffu, dot, o);
            ny  += __shfl_xor_sync(0xffffffffu, ny,  o);
        }

        if (sub == 0 && ok) {
            float sq  = nx - 2.0f * dot + ny;
            float arg = 1.0f + 2.0f * sq * inv / (1.0f - ny);
            arg = fmaxf(arg, 1.0f + 1e-7f);
            float d = acoshf(arg);
            g_dleaf[leaf] = __float2half(d);
            dmax = fmaxf(dmax, d);
        }
    }

    // ---- block max -> global atomicMax (deterministic) ----
    s_red[t] = dmax;
    __syncthreads();
    for (int off = 128; off > 0; off >>= 1) {
        if (t < off) s_red[t] = fmaxf(s_red[t], s_red[t + off]);
        __syncthreads();
    }
    if (t == 0) atomicMax(&g_maxint, __float_as_int(s_red[0]));
}

// ---------------- Kernel B: branchless softmax partial sums ----------------
__global__ __launch_bounds__(1024) void pair_reduce_kernel(
        const int* __restrict__ l_idx,
        const int* __restrict__ r_idx,
        const float* __restrict__ sims,
        int n_pairs, int n_leaves)
{
    extern __shared__ __half s_tab[];
    __shared__ float r_se[1024], r_ss[1024], r_su[1024];
    __shared__ __align__(8) unsigned long long s_mbar;

    const int t = threadIdx.x;
    const unsigned int sb  = (unsigned int)__cvta_generic_to_shared(s_tab);
    const unsigned int mbr = (unsigned int)__cvta_generic_to_shared(&s_mbar);

    const unsigned int totr  = ((unsigned int)n_leaves * 2u + 127u) & ~127u;
    const unsigned int chunk = totr / 8u;

    if (t == 0) { mbar_init(mbr, 1); mbar_expect_tx(mbr, totr); }
    __syncthreads();
    if (t < 8)
        bulk_g2s(sb + t * chunk, reinterpret_cast<const char*>(g_dleaf) + t * chunk,
                 chunk, mbr);

    const float M = 40.0f * __int_as_float(g_maxint);

    mbar_wait(mbr, 0);

    float se = 0.0f, ss = 0.0f, su = 0.0f;

    const int n4 = n_pairs >> 2;
    const int4*   l4 = reinterpret_cast<const int4*>(l_idx);
    const int4*   r4 = reinterpret_cast<const int4*>(r_idx);
    const float4* s4 = reinterpret_cast<const float4*>(sims);
    const int stride = gridDim.x * blockDim.x;

    #pragma unroll 2
    for (int i = blockIdx.x * blockDim.x + t; i < n4; i += stride) {
        int4   li = l4[i];
        int4   ri = r4[i];
        float4 si = s4[i];
        float e0 = __expf(fmaf(20.0f, __half2float(s_tab[li.x]) + __half2float(s_tab[ri.x]), -M));
        float e1 = __expf(fmaf(20.0f, __half2float(s_tab[li.y]) + __half2float(s_tab[ri.y]), -M));
        float e2 = __expf(fmaf(20.0f, __half2float(s_tab[li.z]) + __half2float(s_tab[ri.z]), -M));
        float e3 = __expf(fmaf(20.0f, __half2float(s_tab[li.w]) + __half2float(s_tab[ri.w]), -M));
        se += (e0 + e1) + (e2 + e3);
        ss  = fmaf(si.x, e0, fmaf(si.y, e1, fmaf(si.z, e2, fmaf(si.w, e3, ss))));
        su += (si.x + si.y) + (si.z + si.w);
    }
    // scalar tail
    if (blockIdx.x == 0) {
        for (int i = n4 * 4 + t; i < n_pairs; i += blockDim.x) {
            float e = __expf(fmaf(20.0f,
                        __half2float(s_tab[l_idx[i]]) + __half2float(s_tab[r_idx[i]]), -M));
            float si = sims[i];
            se += e; ss = fmaf(si, e, ss); su += si;
        }
    }

    r_se[t] = se; r_ss[t] = ss; r_su[t] = su;
    __syncthreads();
    for (int off = 512; off > 0; off >>= 1) {
        if (t < off) {
            r_se[t] += r_se[t + off];
            r_ss[t] += r_ss[t + off];
            r_su[t] += r_su[t + off];
        }
        __syncthreads();
    }
    if (t == 0) g_part[blockIdx.x] = make_float4(r_se[0], r_ss[0], r_su[0], 0.0f);
}

// ---------------- Kernel C: finalize ----------------
__global__ void finalize_kernel(float* __restrict__ out, int nb)
{
    __shared__ float r_se[256], r_ss[256], r_su[256];
    const int t = threadIdx.x;
    float se = 0.0f, ss = 0.0f, su = 0.0f;
    for (int i = t; i < nb; i += 256) {
        float4 p = g_part[i];
        se += p.x; ss += p.y; su += p.z;
    }
    r_se[t] = se; r_ss[t] = ss; r_su[t] = su;
    __syncthreads();
    for (int off = 128; off > 0; off >>= 1) {
        if (t < off) {
            r_se[t] += r_se[t + off];
            r_ss[t] += r_ss[t + off];
            r_su[t] += r_su[t + off];
        }
        __syncthreads();
    }
    if (t == 0) out[0] = r_su[0] - r_ss[0] / r_se[0];
}

// ---------------- launch ----------------
extern "C" void kernel_launch(void* const* d_in, const int* in_sizes, int n_in,
                              void* d_out, int out_size)
{
    const int*   lca    = (const int*)  d_in[0];
    const int*   l_idx  = (const int*)  d_in[1];
    const int*   r_idx  = (const int*)  d_in[2];
    const float* sims   = (const float*)d_in[3];
    const float* emb    = (const float*)d_in[4];
    const float* leaves = (const float*)d_in[5];
    const float* scale  = (const float*)d_in[6];

    const int n_pairs  = in_sizes[1];
    const int n_leaves = in_sizes[5] / 128;

    const int smemB = (n_leaves * 2 + 127) & ~127;
    cudaFuncSetAttribute(pair_reduce_kernel,
                         cudaFuncAttributeMaxDynamicSharedMemorySize,
                         (N_LEAVES_MAX * 2 + 127) & ~127);

    int sm_count = 0;
    cudaDeviceGetAttribute(&sm_count, cudaDevAttrMultiProcessorCount, 0);
    if (sm_count <= 0 || sm_count > MAXB) sm_count = 148;

    leaf_dist_kernel<<<sm_count * 2, 256>>>(lca, emb, leaves, scale, n_leaves);
    pair_reduce_kernel<<<GRID_B, 1024, smemB>>>(l_idx, r_idx, sims, n_pairs, n_leaves);
    finalize_kernel<<<1, 256>>>((float*)d_out, GRID_B);
}

// round 10
// speedup vs baseline: 1.2301x; 1.1100x over previous
#include <cuda_runtime.h>
#include <cuda_fp16.h>
#include <cstdint>
#include <math.h>

// ---------------- scratch (no allocations allowed) ----------------
#define N_LEAVES_MAX 100000
#define MAXB 256
#define GRID_B 148

__device__ __align__(16) __half g_dleaf[N_LEAVES_MAX + 128];
__device__ int    g_maxint;          // max d as ordered int (positive floats)
__device__ float4 g_part[MAXB];      // (sum_exp, sum_sims_exp, sum_sims, -)

// ---------------- mbarrier / bulk-copy helpers (kernel B staging) ----------------
__device__ __forceinline__ void mbar_init(unsigned int mbar, unsigned int cnt) {
    asm volatile("mbarrier.init.shared.b64 [%0], %1;" :: "r"(mbar), "r"(cnt) : "memory");
}
__device__ __forceinline__ void mbar_expect_tx(unsigned int mbar, unsigned int bytes) {
    asm volatile("mbarrier.arrive.expect_tx.shared.b64 _, [%0], %1;"
                 :: "r"(mbar), "r"(bytes) : "memory");
}
__device__ __forceinline__ void mbar_wait(unsigned int mbar, unsigned int phase) {
    asm volatile(
        "{\n\t"
        ".reg .pred P1;\n\t"
        "WAIT_LOOP_%=:\n\t"
        "mbarrier.try_wait.parity.acquire.cta.shared::cta.b64 P1, [%0], %1, 0x989680;\n\t"
        "@P1 bra.uni WAIT_DONE_%=;\n\t"
        "bra.uni WAIT_LOOP_%=;\n\t"
        "WAIT_DONE_%=:\n\t"
        "}"
        :: "r"(mbar), "r"(phase) : "memory");
}
__device__ __forceinline__ void bulk_g2s(unsigned int dst, const void* src,
                                         unsigned int bytes, unsigned int mbar) {
    asm volatile(
        "cp.async.bulk.shared::cluster.global.mbarrier::complete_tx::bytes [%0], [%1], %2, [%3];"
        :: "r"(dst), "l"(src), "r"(bytes), "r"(mbar) : "memory");
}

// ---------------- Kernel A: direct-LDG streaming, 8 leaves / warp-iter ----------------
// lane: grp = lane>>3 (leaf within group-of-4), sub = lane&7 (16B chunk slot).
// Each warp-iteration covers 2 groups (8 leaves) = 8 LDG.128 in flight.
__global__ __launch_bounds__(256, 4) void leaf_dist_kernel(
        const int* __restrict__ lca,
        const float* __restrict__ emb,
        const float* __restrict__ leaves,
        const float* __restrict__ scale,
        int n_leaves)
{
    __shared__ __align__(16) float s_e[128];
    __shared__ float s_red[256];
    __shared__ float s_nx, s_inv;

    const int t = threadIdx.x;

    // ---- build e1 = emb[lca]/max(||.||,1e-12) * clip(scale) ----
    const float* erow = emb + (long long)lca[0] * 128;
    float w = 0.0f;
    if (t < 128) { w = erow[t]; s_red[t] = w * w; }
    __syncthreads();
    for (int off = 64; off > 0; off >>= 1) {
        if (t < off) s_red[t] += s_red[t + off];
        __syncthreads();
    }
    if (t == 0) {
        float norm2  = s_red[0];
        float s      = fminf(fmaxf(scale[0], 0.01f), 1.0f - 0.001f);
        float factor = s / fmaxf(sqrtf(norm2), 1e-12f);
        float nx     = factor * factor * norm2;
        s_nx  = nx;
        s_inv = 1.0f / (1.0f - nx);
        s_red[0] = factor;
    }
    __syncthreads();
    if (t < 128) s_e[t] = w * s_red[0];
    __syncthreads();

    const int lane = t & 31;
    const int sub  = lane & 7;
    const int grp  = lane >> 3;
    const float4* er = reinterpret_cast<const float4*>(s_e);
    const float4 ea = er[sub], eb = er[sub + 8], ec = er[sub + 16], ed = er[sub + 24];
    const float nx = s_nx, inv = s_inv;

    const float4* leaves4 = reinterpret_cast<const float4*>(leaves);
    const int gwarp   = (blockIdx.x * blockDim.x + t) >> 5;
    const int nwarps  = (gridDim.x * blockDim.x) >> 5;
    const int ngrp8   = (n_leaves + 7) >> 3;     // groups of 8 leaves

    float dmax = 0.0f;

    for (int g8 = gwarp; g8 < ngrp8; g8 += nwarps) {
        const int  leafA = g8 * 8 + grp;
        const int  leafB = leafA + 4;
        const bool okA   = leafA < n_leaves;
        const bool okB   = leafB < n_leaves;
        const float4* rowA = leaves4 + (size_t)(okA ? leafA : 0) * 32;
        const float4* rowB = leaves4 + (size_t)(okB ? leafB : 0) * 32;

        // issue all 8 LDG.128 before any consumption
        float4 a0 = rowA[sub];
        float4 a1 = rowA[sub + 8];
        float4 a2 = rowA[sub + 16];
        float4 a3 = rowA[sub + 24];
        float4 b0 = rowB[sub];
        float4 b1 = rowB[sub + 8];
        float4 b2 = rowB[sub + 16];
        float4 b3 = rowB[sub + 24];

        // ---- group A ----
        float dotA, nyA;
        dotA = ea.x * a0.x + ea.y * a0.y + ea.z * a0.z + ea.w * a0.w;
        nyA  = a0.x * a0.x + a0.y * a0.y + a0.z * a0.z + a0.w * a0.w;
        dotA = fmaf(eb.x, a1.x, fmaf(eb.y, a1.y, fmaf(eb.z, a1.z, fmaf(eb.w, a1.w, dotA))));
        nyA  = fmaf(a1.x, a1.x, fmaf(a1.y, a1.y, fmaf(a1.z, a1.z, fmaf(a1.w, a1.w, nyA))));
        dotA = fmaf(ec.x, a2.x, fmaf(ec.y, a2.y, fmaf(ec.z, a2.z, fmaf(ec.w, a2.w, dotA))));
        nyA  = fmaf(a2.x, a2.x, fmaf(a2.y, a2.y, fmaf(a2.z, a2.z, fmaf(a2.w, a2.w, nyA))));
        dotA = fmaf(ed.x, a3.x, fmaf(ed.y, a3.y, fmaf(ed.z, a3.z, fmaf(ed.w, a3.w, dotA))));
        nyA  = fmaf(a3.x, a3.x, fmaf(a3.y, a3.y, fmaf(a3.z, a3.z, fmaf(a3.w, a3.w, nyA))));

        // ---- group B ----
        float dotB, nyB;
        dotB = ea.x * b0.x + ea.y * b0.y + ea.z * b0.z + ea.w * b0.w;
        nyB  = b0.x * b0.x + b0.y * b0.y + b0.z * b0.z + b0.w * b0.w;
        dotB = fmaf(eb.x, b1.x, fmaf(eb.y, b1.y, fmaf(eb.z, b1.z, fmaf(eb.w, b1.w, dotB))));
        nyB  = fmaf(b1.x, b1.x, fmaf(b1.y, b1.y, fmaf(b1.z, b1.z, fmaf(b1.w, b1.w, nyB))));
        dotB = fmaf(ec.x, b2.x, fmaf(ec.y, b2.y, fmaf(ec.z, b2.z, fmaf(ec.w, b2.w, dotB))));
        nyB  = fmaf(b2.x, b2.x, fmaf(b2.y, b2.y, fmaf(b2.z, b2.z, fmaf(b2.w, b2.w, nyB))));
        dotB = fmaf(ed.x, b3.x, fmaf(ed.y, b3.y, fmaf(ed.z, b3.z, fmaf(ed.w, b3.w, dotB))));
        nyB  = fmaf(b3.x, b3.x, fmaf(b3.y, b3.y, fmaf(b3.z, b3.z, fmaf(b3.w, b3.w, nyB))));

        #pragma unroll
        for (int o = 1; o < 8; o <<= 1) {
            dotA += __shfl_xor_sync(0xffffffffu, dotA, o);
            nyA  += __shfl_xor_sync(0xffffffffu, nyA,  o);
            dotB += __shfl_xor_sync(0xffffffffu, dotB, o);
            nyB  += __shfl_xor_sync(0xffffffffu, nyB,  o);
        }

        if (sub == 0) {
            if (okA) {
                float sq  = nx - 2.0f * dotA + nyA;
                float arg = fmaxf(1.0f + 2.0f * sq * inv / (1.0f - nyA), 1.0f + 1e-7f);
                float d = acoshf(arg);
                g_dleaf[leafA] = __float2half(d);
                dmax = fmaxf(dmax, d);
            }
            if (okB) {
                float sq  = nx - 2.0f * dotB + nyB;
                float arg = fmaxf(1.0f + 2.0f * sq * inv / (1.0f - nyB), 1.0f + 1e-7f);
                float d = acoshf(arg);
                g_dleaf[leafB] = __float2half(d);
                dmax = fmaxf(dmax, d);
            }
        }
    }

    // ---- block max -> global atomicMax (deterministic) ----
    s_red[t] = dmax;
    __syncthreads();
    for (int off = 128; off > 0; off >>= 1) {
        if (t < off) s_red[t] = fmaxf(s_red[t], s_red[t + off]);
        __syncthreads();
    }
    if (t == 0) atomicMax(&g_maxint, __float_as_int(s_red[0]));
}

// ---------------- Kernel B: branchless softmax partial sums ----------------
__global__ __launch_bounds__(1024) void pair_reduce_kernel(
        const int* __restrict__ l_idx,
        const int* __restrict__ r_idx,
        const float* __restrict__ sims,
        int n_pairs, int n_leaves)
{
    extern __shared__ __half s_tab[];
    __shared__ float r_se[1024], r_ss[1024], r_su[1024];
    __shared__ __align__(8) unsigned long long s_mbar;

    const int t = threadIdx.x;
    const unsigned int sb  = (unsigned int)__cvta_generic_to_shared(s_tab);
    const unsigned int mbr = (unsigned int)__cvta_generic_to_shared(&s_mbar);

    const unsigned int totr  = ((unsigned int)n_leaves * 2u + 127u) & ~127u;
    const unsigned int chunk = totr / 8u;

    if (t == 0) { mbar_init(mbr, 1); mbar_expect_tx(mbr, totr); }
    __syncthreads();
    if (t < 8)
        bulk_g2s(sb + t * chunk, reinterpret_cast<const char*>(g_dleaf) + t * chunk,
                 chunk, mbr);

    const float M = 40.0f * __int_as_float(g_maxint);

    mbar_wait(mbr, 0);

    float se = 0.0f, ss = 0.0f, su = 0.0f;

    const int n4 = n_pairs >> 2;
    const int4*   l4 = reinterpret_cast<const int4*>(l_idx);
    const int4*   r4 = reinterpret_cast<const int4*>(r_idx);
    const float4* s4 = reinterpret_cast<const float4*>(sims);
    const int stride = gridDim.x * blockDim.x;

    #pragma unroll 2
    for (int i = blockIdx.x * blockDim.x + t; i < n4; i += stride) {
        int4   li = l4[i];
        int4   ri = r4[i];
        float4 si = s4[i];
        float e0 = __expf(fmaf(20.0f, __half2float(s_tab[li.x]) + __half2float(s_tab[ri.x]), -M));
        float e1 = __expf(fmaf(20.0f, __half2float(s_tab[li.y]) + __half2float(s_tab[ri.y]), -M));
        float e2 = __expf(fmaf(20.0f, __half2float(s_tab[li.z]) + __half2float(s_tab[ri.z]), -M));
        float e3 = __expf(fmaf(20.0f, __half2float(s_tab[li.w]) + __half2float(s_tab[ri.w]), -M));
        se += (e0 + e1) + (e2 + e3);
        ss  = fmaf(si.x, e0, fmaf(si.y, e1, fmaf(si.z, e2, fmaf(si.w, e3, ss))));
        su += (si.x + si.y) + (si.z + si.w);
    }
    // scalar tail
    if (blockIdx.x == 0) {
        for (int i = n4 * 4 + t; i < n_pairs; i += blockDim.x) {
            float e = __expf(fmaf(20.0f,
                        __half2float(s_tab[l_idx[i]]) + __half2float(s_tab[r_idx[i]]), -M));
            float si = sims[i];
            se += e; ss = fmaf(si, e, ss); su += si;
        }
    }

    r_se[t] = se; r_ss[t] = ss; r_su[t] = su;
    __syncthreads();
    for (int off = 512; off > 0; off >>= 1) {
        if (t < off) {
            r_se[t] += r_se[t + off];
            r_ss[t] += r_ss[t + off];
            r_su[t] += r_su[t + off];
        }
        __syncthreads();
    }
    if (t == 0) g_part[blockIdx.x] = make_float4(r_se[0], r_ss[0], r_su[0], 0.0f);
}

// ---------------- Kernel C: finalize ----------------
__global__ void finalize_kernel(float* __restrict__ out, int nb)
{
    __shared__ float r_se[256], r_ss[256], r_su[256];
    const int t = threadIdx.x;
    float se = 0.0f, ss = 0.0f, su = 0.0f;
    for (int i = t; i < nb; i += 256) {
        float4 p = g_part[i];
        se += p.x; ss += p.y; su += p.z;
    }
    r_se[t] = se; r_ss[t] = ss; r_su[t] = su;
    __syncthreads();
    for (int off = 128; off > 0; off >>= 1) {
        if (t < off) {
            r_se[t] += r_se[t + off];
            r_ss[t] += r_ss[t + off];
            r_su[t] += r_su[t + off];
        }
        __syncthreads();
    }
    if (t == 0) out[0] = r_su[0] - r_ss[0] / r_se[0];
}

// ---------------- launch ----------------
extern "C" void kernel_launch(void* const* d_in, const int* in_sizes, int n_in,
                              void* d_out, int out_size)
{
    const int*   lca    = (const int*)  d_in[0];
    const int*   l_idx  = (const int*)  d_in[1];
    const int*   r_idx  = (const int*)  d_in[2];
    const float* sims   = (const float*)d_in[3];
    const float* emb    = (const float*)d_in[4];
    const float* leaves = (const float*)d_in[5];
    const float* scale  = (const float*)d_in[6];

    const int n_pairs  = in_sizes[1];
    const int n_leaves = in_sizes[5] / 128;

    const int smemB = (n_leaves * 2 + 127) & ~127;
    cudaFuncSetAttribute(pair_reduce_kernel,
                         cudaFuncAttributeMaxDynamicSharedMemorySize,
                         (N_LEAVES_MAX * 2 + 127) & ~127);

    int sm_count = 0;
    cudaDeviceGetAttribute(&sm_count, cudaDevAttrMultiProcessorCount, 0);
    if (sm_count <= 0 || sm_count > MAXB) sm_count = 148;

    leaf_dist_kernel<<<sm_count * 4, 256>>>(lca, emb, leaves, scale, n_leaves);
    pair_reduce_kernel<<<GRID_B, 1024, smemB>>>(l_idx, r_idx, sims, n_pairs, n_leaves);
    finalize_kernel<<<1, 256>>>((float*)d_out, GRID_B);
}